// round 1
// baseline (speedup 1.0000x reference)
#include <cuda_runtime.h>
#include <math.h>
#include <stdint.h>

#define FULLMASK 0xffffffffu

// ---------------- persistent device scratch (no runtime allocation) ----------------
__device__ float g_W0T[1536 * 2048];   // layer0 weights, [k][j*4+gate], 12.6 MB
__device__ float g_W1T[1024 * 2048];   // layer1 weights, [k][j*4+gate],  8.4 MB
__device__ float g_b0[2048];           // summed biases, interleaved [j*4+gate]
__device__ float g_b1[2048];
__device__ float g_emb[32 * 64 * 512]; // gathered embeddings [b][t][k]
__device__ float g_f1[32 * 512];       // hidden of feature MLP layer 1
__device__ float g_h0[2][32 * 512];    // parity-double-buffered hidden states
__device__ float g_h1[2][32 * 512];
__device__ float g_c0[32 * 512];       // cell states (updated in place, per-thread)
__device__ float g_c1[32 * 512];
__device__ float g_ctx[32 * 512];      // attention context
__device__ float g_hs[2048 * 512];     // all layer-1 hiddens, row m = t*32+b

// ---------------- helpers ----------------
static __device__ __forceinline__ float sigmoidf_(float x) { return 1.f / (1.f + expf(-x)); }

static __device__ __forceinline__ float warp_sum(float v) {
#pragma unroll
    for (int o = 16; o; o >>= 1) v += __shfl_xor_sync(FULLMASK, v, o);
    return v;
}

// packed fp32x2 (sm_100+): 2x fp32 FMA throughput
static __device__ __forceinline__ unsigned long long pack2(float lo, float hi) {
    unsigned long long r;
    asm("mov.b64 %0, {%1, %2};" : "=l"(r) : "f"(lo), "f"(hi));
    return r;
}
static __device__ __forceinline__ void unpack2(unsigned long long v, float& lo, float& hi) {
    asm("mov.b64 {%0, %1}, %2;" : "=f"(lo), "=f"(hi) : "l"(v));
}
#define FMA2(acc, a, b) asm("fma.rn.f32x2 %0, %1, %2, %0;" : "+l"(acc) : "l"(a), "l"(b))

// ---------------- weight preprocessing ----------------
// W0T[k][j*4+g] = wcat0[g*512+j][k], wcat0 = [w_ih0 | w_hh0] along k (1024 + 512)
__global__ __launch_bounds__(256) void prepW0_kernel(const float* __restrict__ wih0,
                                                     const float* __restrict__ whh0) {
    int idx = blockIdx.x * 256 + threadIdx.x;      // < 1536*2048
    int k = idx >> 11;
    int jj = idx & 2047;
    int j = jj >> 2, g = jj & 3;
    int row = g * 512 + j;
    float v = (k < 1024) ? wih0[row * 1024 + k] : whh0[row * 512 + (k - 1024)];
    g_W0T[idx] = v;
}

// W1T[k][j*4+g] = wcat1[g*512+j][k], wcat1 = [w_ih1 | w_hh1] along k (512 + 512)
__global__ __launch_bounds__(256) void prepW1_kernel(const float* __restrict__ wih1,
                                                     const float* __restrict__ whh1) {
    int idx = blockIdx.x * 256 + threadIdx.x;      // < 1024*2048
    int k = idx >> 11;
    int jj = idx & 2047;
    int j = jj >> 2, g = jj & 3;
    int row = g * 512 + j;
    float v = (k < 512) ? wih1[row * 512 + k] : whh1[row * 512 + (k - 512)];
    g_W1T[idx] = v;
}

__global__ __launch_bounds__(256) void prepB_kernel(const float* __restrict__ bih0,
                                                    const float* __restrict__ bhh0,
                                                    const float* __restrict__ bih1,
                                                    const float* __restrict__ bhh1) {
    int jj = blockIdx.x * 256 + threadIdx.x;       // < 2048
    int j = jj >> 2, g = jj & 3;
    int row = g * 512 + j;
    g_b0[jj] = bih0[row] + bhh0[row];
    g_b1[jj] = bih1[row] + bhh1[row];
}

// ---------------- embedding gather ----------------
__global__ __launch_bounds__(256) void embed_kernel(const int* __restrict__ cap,
                                                    const float* __restrict__ table) {
    int idx = blockIdx.x * 256 + threadIdx.x;      // < 32*64*512
    int w = idx >> 9;                              // b*64 + t
    int k = idx & 511;
    int tok = cap[w];
    g_emb[idx] = table[(size_t)tok * 512 + k];
}

// ---------------- feature MLP ----------------
// warp per output (b,j): f1 = relu(features @ ft1_w^T + b1)
__global__ __launch_bounds__(256) void feat1_kernel(const float* __restrict__ features,
                                                    const float* __restrict__ w,
                                                    const float* __restrict__ bias) {
    int gid = blockIdx.x * 8 + (threadIdx.x >> 5); // < 16384
    int lane = threadIdx.x & 31;
    int b = gid >> 9, j = gid & 511;
    const float* fr = features + b * 2048;
    const float* wr = w + j * 2048;
    float a = 0.f;
    for (int k = lane; k < 2048; k += 32) a = fmaf(fr[k], wr[k], a);
    a = warp_sum(a);
    if (!lane) g_f1[gid] = fmaxf(a + bias[j], 0.f);
}

// f2 = f1 @ ft2_w^T + b2 ; initializes h0, h1, c0, c1 (parity buffer 0)
__global__ __launch_bounds__(256) void feat2_kernel(const float* __restrict__ w,
                                                    const float* __restrict__ bias) {
    int gid = blockIdx.x * 8 + (threadIdx.x >> 5);
    int lane = threadIdx.x & 31;
    int b = gid >> 9, j = gid & 511;
    const float* fr = g_f1 + b * 512;
    const float* wr = w + j * 512;
    float a = 0.f;
    for (int k = lane; k < 512; k += 32) a = fmaf(fr[k], wr[k], a);
    a = warp_sum(a);
    if (!lane) {
        float v = a + bias[j];
        g_h0[0][gid] = v;
        g_h1[0][gid] = v;
        g_c0[gid] = v;
        g_c1[gid] = v;
    }
}

// ---------------- attention (one block per batch element) ----------------
__global__ __launch_bounds__(256) void attn_kernel(const float* __restrict__ enc, int pin) {
    __shared__ float q[512];
    __shared__ float sc[196];
    __shared__ float redm[8];
    __shared__ float reds[8];
    int b = blockIdx.x;
    int tid = threadIdx.x, lane = tid & 31, wid = tid >> 5;

    for (int i = tid; i < 512; i += 256) q[i] = g_h1[pin][b * 512 + i];
    __syncthreads();

    // scores: warp per score row
    for (int s = wid; s < 196; s += 8) {
        const float* e = enc + ((size_t)b * 196 + s) * 512;
        float a = 0.f;
        for (int k = lane; k < 512; k += 32) a = fmaf(q[k], e[k], a);
        a = warp_sum(a);
        if (!lane) sc[s] = a * 0.04419417382415922f;  // 1/sqrt(512)
    }
    __syncthreads();

    // softmax over 196
    float v = (tid < 196) ? sc[tid] : -1e30f;
    float m = v;
#pragma unroll
    for (int o = 16; o; o >>= 1) m = fmaxf(m, __shfl_xor_sync(FULLMASK, m, o));
    if (!lane) redm[wid] = m;
    __syncthreads();
    m = redm[0];
#pragma unroll
    for (int i = 1; i < 8; i++) m = fmaxf(m, redm[i]);
    float ev = (tid < 196) ? expf(v - m) : 0.f;
    float s = warp_sum(ev);
    if (!lane) reds[wid] = s;
    __syncthreads();
    s = 0.f;
#pragma unroll
    for (int i = 0; i < 8; i++) s += reds[i];
    if (tid < 196) sc[tid] = ev / s;
    __syncthreads();

    // ctx[j] = sum_s a[s] * enc[b][s][j]
    for (int j = tid; j < 512; j += 256) {
        const float* e = enc + (size_t)b * 196 * 512 + j;
        float a = 0.f;
#pragma unroll 4
        for (int ss = 0; ss < 196; ss++) a = fmaf(sc[ss], e[(size_t)ss * 512], a);
        g_ctx[b * 512 + j] = a;
    }
}

// ---------------- LSTM layer 0 ----------------
// grid (8, 32): blockIdx.y = b, 64 hidden units per block, K split into 2 halves.
// Each thread computes all 4 gates for one hidden unit (interleaved weight layout).
__global__ __launch_bounds__(128) void lstm0_kernel(int t, int pin, int pout) {
    __shared__ float x[1536];
    __shared__ float4 part[64];
    int b = blockIdx.y;
    int tid = threadIdx.x;
    for (int i = tid; i < 512; i += 128) x[i] = g_emb[(b * 64 + t) * 512 + i];
    for (int i = tid; i < 512; i += 128) x[512 + i] = g_ctx[b * 512 + i];
    for (int i = tid; i < 512; i += 128) x[1024 + i] = g_h0[pin][b * 512 + i];
    __syncthreads();

    int half = tid >> 6, lj = tid & 63;
    int j = blockIdx.x * 64 + lj;
    const float4* W = (const float4*)g_W0T + half * 768 * 512 + j;
    const float* xp = x + half * 768;
    float4 acc = make_float4(0.f, 0.f, 0.f, 0.f);
#pragma unroll 8
    for (int k = 0; k < 768; k++) {
        float xv = xp[k];
        float4 w = W[k * 512];
        acc.x = fmaf(w.x, xv, acc.x);
        acc.y = fmaf(w.y, xv, acc.y);
        acc.z = fmaf(w.z, xv, acc.z);
        acc.w = fmaf(w.w, xv, acc.w);
    }
    if (half) part[lj] = acc;
    __syncthreads();
    if (!half) {
        float4 p = part[lj];
        float4 bs = ((const float4*)g_b0)[j];
        float gi = sigmoidf_(acc.x + p.x + bs.x);
        float gf = sigmoidf_(acc.y + p.y + bs.y);
        float gg = tanhf(acc.z + p.z + bs.z);
        float go = sigmoidf_(acc.w + p.w + bs.w);
        float c = g_c0[b * 512 + j];
        float c2 = gf * c + gi * gg;
        g_c0[b * 512 + j] = c2;
        g_h0[pout][b * 512 + j] = go * tanhf(c2);
    }
}

// ---------------- LSTM layer 1 ----------------
__global__ __launch_bounds__(128) void lstm1_kernel(int t, int pin, int pout) {
    __shared__ float x[1024];
    __shared__ float4 part[64];
    int b = blockIdx.y;
    int tid = threadIdx.x;
    for (int i = tid; i < 512; i += 128) x[i] = g_h0[pout][b * 512 + i];        // h0n (just written)
    for (int i = tid; i < 512; i += 128) x[512 + i] = g_h1[pin][b * 512 + i];   // h1 prev
    __syncthreads();

    int half = tid >> 6, lj = tid & 63;
    int j = blockIdx.x * 64 + lj;
    const float4* W = (const float4*)g_W1T + half * 512 * 512 + j;
    const float* xp = x + half * 512;
    float4 acc = make_float4(0.f, 0.f, 0.f, 0.f);
#pragma unroll 8
    for (int k = 0; k < 512; k++) {
        float xv = xp[k];
        float4 w = W[k * 512];
        acc.x = fmaf(w.x, xv, acc.x);
        acc.y = fmaf(w.y, xv, acc.y);
        acc.z = fmaf(w.z, xv, acc.z);
        acc.w = fmaf(w.w, xv, acc.w);
    }
    if (half) part[lj] = acc;
    __syncthreads();
    if (!half) {
        float4 p = part[lj];
        float4 bs = ((const float4*)g_b1)[j];
        float gi = sigmoidf_(acc.x + p.x + bs.x);
        float gf = sigmoidf_(acc.y + p.y + bs.y);
        float gg = tanhf(acc.z + p.z + bs.z);
        float go = sigmoidf_(acc.w + p.w + bs.w);
        float c = g_c1[b * 512 + j];
        float c2 = gf * c + gi * gg;
        g_c1[b * 512 + j] = c2;
        float h = go * tanhf(c2);
        g_h1[pout][b * 512 + j] = h;
        g_hs[((size_t)t * 32 + b) * 512 + j] = h;
    }
}

// ---------------- final FC: [2048,512] x [512,32000] + bias ----------------
// 128x128 tile, 8x8 per thread held as 32 packed f32x2 accumulators (FFMA2 pipe).
__global__ __launch_bounds__(256) void fc_kernel(const float* __restrict__ fcw,
                                                 const float* __restrict__ fcb,
                                                 float* __restrict__ out) {
    __shared__ float As[16][132];
    __shared__ float Bs[16][132];
    int tid = threadIdx.x;
    int mb = blockIdx.y * 128, nb = blockIdx.x * 128;
    int ar = tid >> 1;
    int ak = (tid & 1) * 8;
    int ty = tid >> 4, tx = tid & 15;
    const float* Ag = g_hs + (size_t)(mb + ar) * 512 + ak;
    const float* Bg = fcw + (size_t)(nb + ar) * 512 + ak;

    unsigned long long acc[8][4];
#pragma unroll
    for (int i = 0; i < 8; i++)
#pragma unroll
        for (int jj = 0; jj < 4; jj++) acc[i][jj] = 0ull;

    for (int kt = 0; kt < 512; kt += 16) {
        float4 a0 = *(const float4*)(Ag + kt);
        float4 a1 = *(const float4*)(Ag + kt + 4);
        float4 b0 = *(const float4*)(Bg + kt);
        float4 b1 = *(const float4*)(Bg + kt + 4);
        __syncthreads();
        As[ak + 0][ar] = a0.x; As[ak + 1][ar] = a0.y; As[ak + 2][ar] = a0.z; As[ak + 3][ar] = a0.w;
        As[ak + 4][ar] = a1.x; As[ak + 5][ar] = a1.y; As[ak + 6][ar] = a1.z; As[ak + 7][ar] = a1.w;
        Bs[ak + 0][ar] = b0.x; Bs[ak + 1][ar] = b0.y; Bs[ak + 2][ar] = b0.z; Bs[ak + 3][ar] = b0.w;
        Bs[ak + 4][ar] = b1.x; Bs[ak + 5][ar] = b1.y; Bs[ak + 6][ar] = b1.z; Bs[ak + 7][ar] = b1.w;
        __syncthreads();
#pragma unroll
        for (int k = 0; k < 16; k++) {
            float4 av0 = *(const float4*)&As[k][ty * 8];
            float4 av1 = *(const float4*)&As[k][ty * 8 + 4];
            ulonglong2 bb0 = *(const ulonglong2*)&Bs[k][tx * 8];
            ulonglong2 bb1 = *(const ulonglong2*)&Bs[k][tx * 8 + 4];
            unsigned long long bv0 = bb0.x, bv1 = bb0.y, bv2 = bb1.x, bv3 = bb1.y;
            float a[8] = {av0.x, av0.y, av0.z, av0.w, av1.x, av1.y, av1.z, av1.w};
#pragma unroll
            for (int i = 0; i < 8; i++) {
                unsigned long long aa = pack2(a[i], a[i]);
                FMA2(acc[i][0], aa, bv0);
                FMA2(acc[i][1], aa, bv1);
                FMA2(acc[i][2], aa, bv2);
                FMA2(acc[i][3], aa, bv3);
            }
        }
    }

    int m0 = mb + ty * 8;
    int n0 = nb + tx * 8;
    float4 e0 = *(const float4*)(fcb + n0);
    float4 e1 = *(const float4*)(fcb + n0 + 4);
    float bias[8] = {e0.x, e0.y, e0.z, e0.w, e1.x, e1.y, e1.z, e1.w};
#pragma unroll
    for (int i = 0; i < 8; i++) {
        float c[8];
        unpack2(acc[i][0], c[0], c[1]);
        unpack2(acc[i][1], c[2], c[3]);
        unpack2(acc[i][2], c[4], c[5]);
        unpack2(acc[i][3], c[6], c[7]);
        float4 o0 = make_float4(c[0] + bias[0], c[1] + bias[1], c[2] + bias[2], c[3] + bias[3]);
        float4 o1 = make_float4(c[4] + bias[4], c[5] + bias[5], c[6] + bias[6], c[7] + bias[7]);
        size_t ro = (size_t)(m0 + i) * 32000 + n0;
        *(float4*)(out + ro) = o0;
        *(float4*)(out + ro + 4) = o1;
    }
}

// ---------------- launch ----------------
extern "C" void kernel_launch(void* const* d_in, const int* in_sizes, int n_in,
                              void* d_out, int out_size) {
    (void)in_sizes; (void)n_in; (void)out_size;
    const float* features = (const float*)d_in[0];
    const int*   captions = (const int*)d_in[1];
    // d_in[2] = lengths (all == L, unused)
    const float* enc   = (const float*)d_in[3];
    const float* table = (const float*)d_in[4];
    const float* ft1w  = (const float*)d_in[5];
    const float* ft1b  = (const float*)d_in[6];
    const float* ft2w  = (const float*)d_in[7];
    const float* ft2b  = (const float*)d_in[8];
    const float* wih0  = (const float*)d_in[9];
    const float* whh0  = (const float*)d_in[10];
    const float* bih0  = (const float*)d_in[11];
    const float* bhh0  = (const float*)d_in[12];
    const float* wih1  = (const float*)d_in[13];
    const float* whh1  = (const float*)d_in[14];
    const float* bih1  = (const float*)d_in[15];
    const float* bhh1  = (const float*)d_in[16];
    const float* fcw   = (const float*)d_in[17];
    const float* fcb   = (const float*)d_in[18];
    float* out = (float*)d_out;

    prepW0_kernel<<<12288, 256>>>(wih0, whh0);
    prepW1_kernel<<<8192, 256>>>(wih1, whh1);
    prepB_kernel<<<8, 256>>>(bih0, bhh0, bih1, bhh1);
    embed_kernel<<<4096, 256>>>(captions, table);
    feat1_kernel<<<2048, 256>>>(features, ft1w, ft1b);
    feat2_kernel<<<2048, 256>>>(ft2w, ft2b);

    for (int t = 0; t < 64; t++) {
        int pin = t & 1;
        int pout = pin ^ 1;
        attn_kernel<<<32, 256>>>(enc, pin);
        lstm0_kernel<<<dim3(8, 32), 128>>>(t, pin, pout);
        lstm1_kernel<<<dim3(8, 32), 128>>>(t, pin, pout);
    }

    fc_kernel<<<dim3(250, 16), 256>>>(fcw, fcb, out);
}

// round 2
// speedup vs baseline: 1.6302x; 1.6302x over previous
#include <cuda_runtime.h>
#include <math.h>
#include <stdint.h>

#define FULLMASK 0xffffffffu

// ---------------- persistent device scratch ----------------
__device__ float g_W0T[1536 * 2048];      // layer0 weights [k][j*4+gate]
__device__ float g_W1T[1024 * 2048];      // layer1 weights [k][j*4+gate]
__device__ float g_b0[2048];              // summed biases, interleaved
__device__ float g_b1[2048];
__device__ float g_embT[64 * 512 * 32];   // embeddings [t][k][b]
__device__ float g_f1[32 * 512];          // feature MLP hidden
__device__ float g_h0T[2][512 * 32];      // states [j][b], parity buffered
__device__ float g_h1T[2][512 * 32];
__device__ float g_c0T[512 * 32];
__device__ float g_c1T[512 * 32];
__device__ float g_ctxT[512 * 32];        // attention context [j][b]
__device__ float g_part0[16 * 2048 * 32]; // lstm0 k-split partials [ks][jj][b]
__device__ float g_part1[16 * 2048 * 32];
__device__ float g_hs[2048 * 512];        // FC input, row m = t*32+b

// ---------------- helpers ----------------
static __device__ __forceinline__ float sigmoidf_(float x) { return 1.f / (1.f + expf(-x)); }

static __device__ __forceinline__ float warp_sum(float v) {
#pragma unroll
    for (int o = 16; o; o >>= 1) v += __shfl_xor_sync(FULLMASK, v, o);
    return v;
}

static __device__ __forceinline__ unsigned long long pack2(float lo, float hi) {
    unsigned long long r;
    asm("mov.b64 %0, {%1, %2};" : "=l"(r) : "f"(lo), "f"(hi));
    return r;
}
static __device__ __forceinline__ void unpack2(unsigned long long v, float& lo, float& hi) {
    asm("mov.b64 {%0, %1}, %2;" : "=f"(lo), "=f"(hi) : "l"(v));
}
#define FMA2(acc, a, b) asm("fma.rn.f32x2 %0, %1, %2, %0;" : "+l"(acc) : "l"(a), "l"(b))

// ---------------- weight preprocessing ----------------
__global__ __launch_bounds__(256) void prepW0_kernel(const float* __restrict__ wih0,
                                                     const float* __restrict__ whh0) {
    int idx = blockIdx.x * 256 + threadIdx.x;      // < 1536*2048
    int k = idx >> 11;
    int jj = idx & 2047;
    int j = jj >> 2, g = jj & 3;
    int row = g * 512 + j;
    float v = (k < 1024) ? wih0[row * 1024 + k] : whh0[row * 512 + (k - 1024)];
    g_W0T[idx] = v;
}

__global__ __launch_bounds__(256) void prepW1_kernel(const float* __restrict__ wih1,
                                                     const float* __restrict__ whh1) {
    int idx = blockIdx.x * 256 + threadIdx.x;      // < 1024*2048
    int k = idx >> 11;
    int jj = idx & 2047;
    int j = jj >> 2, g = jj & 3;
    int row = g * 512 + j;
    float v = (k < 512) ? wih1[row * 512 + k] : whh1[row * 512 + (k - 512)];
    g_W1T[idx] = v;
}

__global__ __launch_bounds__(256) void prepB_kernel(const float* __restrict__ bih0,
                                                    const float* __restrict__ bhh0,
                                                    const float* __restrict__ bih1,
                                                    const float* __restrict__ bhh1) {
    int jj = blockIdx.x * 256 + threadIdx.x;       // < 2048
    int j = jj >> 2, g = jj & 3;
    int row = g * 512 + j;
    g_b0[jj] = bih0[row] + bhh0[row];
    g_b1[jj] = bih1[row] + bhh1[row];
}

// ---------------- embedding gather: embT[t][k][b] ----------------
__global__ __launch_bounds__(256) void embed_kernel(const int* __restrict__ cap,
                                                    const float* __restrict__ table) {
    int idx = blockIdx.x * 256 + threadIdx.x;      // < 32*64*512
    int b = idx >> 15;
    int t = (idx >> 9) & 63;
    int k = idx & 511;                             // warp: consecutive k -> coalesced read
    int tok = cap[b * 64 + t];
    g_embT[(t * 512 + k) * 32 + b] = table[(size_t)tok * 512 + k];
}

// ---------------- feature MLP ----------------
__global__ __launch_bounds__(256) void feat1_kernel(const float* __restrict__ features,
                                                    const float* __restrict__ w,
                                                    const float* __restrict__ bias) {
    int gid = blockIdx.x * 8 + (threadIdx.x >> 5); // < 16384
    int lane = threadIdx.x & 31;
    int b = gid >> 9, j = gid & 511;
    const float* fr = features + b * 2048;
    const float* wr = w + j * 2048;
    float a = 0.f;
    for (int k = lane; k < 2048; k += 32) a = fmaf(fr[k], wr[k], a);
    a = warp_sum(a);
    if (!lane) g_f1[gid] = fmaxf(a + bias[j], 0.f);
}

__global__ __launch_bounds__(256) void feat2_kernel(const float* __restrict__ w,
                                                    const float* __restrict__ bias) {
    int gid = blockIdx.x * 8 + (threadIdx.x >> 5);
    int lane = threadIdx.x & 31;
    int b = gid >> 9, j = gid & 511;
    const float* fr = g_f1 + b * 512;
    const float* wr = w + j * 512;
    float a = 0.f;
    for (int k = lane; k < 512; k += 32) a = fmaf(fr[k], wr[k], a);
    a = warp_sum(a);
    if (!lane) {
        float v = a + bias[j];
        int jb = j * 32 + b;
        g_h0T[0][jb] = v;
        g_h1T[0][jb] = v;
        g_c0T[jb] = v;
        g_c1T[jb] = v;
    }
}

// ---------------- attention (one block per batch element) ----------------
__global__ __launch_bounds__(256) void attn_kernel(const float* __restrict__ enc, int pin) {
    __shared__ float q[512];
    __shared__ float sc[196];
    __shared__ float redm[8];
    __shared__ float reds[8];
    int b = blockIdx.x;
    int tid = threadIdx.x, lane = tid & 31, wid = tid >> 5;

    for (int i = tid; i < 512; i += 256) q[i] = g_h1T[pin][i * 32 + b];
    __syncthreads();

    for (int s = wid; s < 196; s += 8) {
        const float* e = enc + ((size_t)b * 196 + s) * 512;
        float a = 0.f;
        for (int k = lane; k < 512; k += 32) a = fmaf(q[k], e[k], a);
        a = warp_sum(a);
        if (!lane) sc[s] = a * 0.04419417382415922f;
    }
    __syncthreads();

    float v = (tid < 196) ? sc[tid] : -1e30f;
    float m = v;
#pragma unroll
    for (int o = 16; o; o >>= 1) m = fmaxf(m, __shfl_xor_sync(FULLMASK, m, o));
    if (!lane) redm[wid] = m;
    __syncthreads();
    m = redm[0];
#pragma unroll
    for (int i = 1; i < 8; i++) m = fmaxf(m, redm[i]);
    float ev = (tid < 196) ? expf(v - m) : 0.f;
    float s = warp_sum(ev);
    if (!lane) reds[wid] = s;
    __syncthreads();
    s = 0.f;
#pragma unroll
    for (int i = 0; i < 8; i++) s += reds[i];
    if (tid < 196) sc[tid] = ev / s;
    __syncthreads();

    for (int j = tid; j < 512; j += 256) {
        const float* e = enc + (size_t)b * 196 * 512 + j;
        float a = 0.f;
#pragma unroll 4
        for (int ss = 0; ss < 196; ss++) a = fmaf(sc[ss], e[(size_t)ss * 512], a);
        g_ctxT[j * 32 + b] = a;
    }
}

// ---------------- LSTM matmul kernels ----------------
// Block (jx, ks): 64 j's x chunk of K x ALL 32 batches. Weight float4 loaded once,
// reused for 32 batches. Thread = (bgroup of 8 b) x (one j, 4 gates).
// Accumulators: 4 gates x 4 b-pairs as packed f32x2.
__global__ __launch_bounds__(256) void lstm0_mm_kernel(int t, int pin) {
    __shared__ float xs[96 * 32];
    int jx = blockIdx.x, ks = blockIdx.y;
    int tid = threadIdx.x;
    int j = tid & 63, bg = tid >> 6;

    const float* embt = g_embT + t * (512 * 32);
    for (int i = tid; i < 96 * 32; i += 256) {
        int kl = i >> 5, b = i & 31;
        int kk = ks * 96 + kl;
        float v;
        if (kk < 512)        v = embt[kk * 32 + b];
        else if (kk < 1024)  v = g_ctxT[(kk - 512) * 32 + b];
        else                 v = g_h0T[pin][(kk - 1024) * 32 + b];
        xs[i] = v;
    }
    __syncthreads();

    int jjbase = (jx * 64 + j) * 4;
    const float4* W = (const float4*)(g_W0T + (size_t)(ks * 96) * 2048 + jjbase);

    unsigned long long acc[4][4];
#pragma unroll
    for (int g = 0; g < 4; g++)
#pragma unroll
        for (int p = 0; p < 4; p++) acc[g][p] = 0ull;

    const float* xr = xs + bg * 8;
#pragma unroll 4
    for (int k = 0; k < 96; k++) {
        float4 w = W[(size_t)k * 512];
        unsigned long long wx = pack2(w.x, w.x);
        unsigned long long wy = pack2(w.y, w.y);
        unsigned long long wz = pack2(w.z, w.z);
        unsigned long long ww = pack2(w.w, w.w);
        const unsigned long long* xp = (const unsigned long long*)(xr + k * 32);
#pragma unroll
        for (int p = 0; p < 4; p++) {
            unsigned long long xv = xp[p];
            FMA2(acc[0][p], wx, xv);
            FMA2(acc[1][p], wy, xv);
            FMA2(acc[2][p], wz, xv);
            FMA2(acc[3][p], ww, xv);
        }
    }

#pragma unroll
    for (int g = 0; g < 4; g++) {
        float* dst = g_part0 + ((size_t)ks * 2048 + jjbase + g) * 32 + bg * 8;
#pragma unroll
        for (int p = 0; p < 4; p++) {
            float lo, hi;
            unpack2(acc[g][p], lo, hi);
            *(float2*)(dst + 2 * p) = make_float2(lo, hi);
        }
    }
}

__global__ __launch_bounds__(256) void lstm1_mm_kernel(int pin, int pout) {
    __shared__ float xs[64 * 32];
    int jx = blockIdx.x, ks = blockIdx.y;
    int tid = threadIdx.x;
    int j = tid & 63, bg = tid >> 6;

    for (int i = tid; i < 64 * 32; i += 256) {
        int kl = i >> 5, b = i & 31;
        int kk = ks * 64 + kl;
        float v = (kk < 512) ? g_h0T[pout][kk * 32 + b]
                             : g_h1T[pin][(kk - 512) * 32 + b];
        xs[i] = v;
    }
    __syncthreads();

    int jjbase = (jx * 64 + j) * 4;
    const float4* W = (const float4*)(g_W1T + (size_t)(ks * 64) * 2048 + jjbase);

    unsigned long long acc[4][4];
#pragma unroll
    for (int g = 0; g < 4; g++)
#pragma unroll
        for (int p = 0; p < 4; p++) acc[g][p] = 0ull;

    const float* xr = xs + bg * 8;
#pragma unroll 4
    for (int k = 0; k < 64; k++) {
        float4 w = W[(size_t)k * 512];
        unsigned long long wx = pack2(w.x, w.x);
        unsigned long long wy = pack2(w.y, w.y);
        unsigned long long wz = pack2(w.z, w.z);
        unsigned long long ww = pack2(w.w, w.w);
        const unsigned long long* xp = (const unsigned long long*)(xr + k * 32);
#pragma unroll
        for (int p = 0; p < 4; p++) {
            unsigned long long xv = xp[p];
            FMA2(acc[0][p], wx, xv);
            FMA2(acc[1][p], wy, xv);
            FMA2(acc[2][p], wz, xv);
            FMA2(acc[3][p], ww, xv);
        }
    }

#pragma unroll
    for (int g = 0; g < 4; g++) {
        float* dst = g_part1 + ((size_t)ks * 2048 + jjbase + g) * 32 + bg * 8;
#pragma unroll
        for (int p = 0; p < 4; p++) {
            float lo, hi;
            unpack2(acc[g][p], lo, hi);
            *(float2*)(dst + 2 * p) = make_float2(lo, hi);
        }
    }
}

// ---------------- gate epilogues (reduce k-split partials) ----------------
__global__ __launch_bounds__(256) void lstm0_red_kernel(int pout) {
    int idx = blockIdx.x * 256 + threadIdx.x;  // < 16384
    int j = idx >> 5, b = idx & 31;
    float s[4];
#pragma unroll
    for (int g = 0; g < 4; g++) s[g] = g_b0[j * 4 + g];
#pragma unroll
    for (int ks = 0; ks < 16; ks++) {
        const float* p = g_part0 + ((size_t)ks * 2048 + j * 4) * 32 + b;
#pragma unroll
        for (int g = 0; g < 4; g++) s[g] += p[g * 32];
    }
    float gi = sigmoidf_(s[0]);
    float gf = sigmoidf_(s[1]);
    float gg = tanhf(s[2]);
    float go = sigmoidf_(s[3]);
    int jb = j * 32 + b;
    float c2 = gf * g_c0T[jb] + gi * gg;
    g_c0T[jb] = c2;
    g_h0T[pout][jb] = go * tanhf(c2);
}

__global__ __launch_bounds__(256) void lstm1_red_kernel(int t, int pout) {
    int idx = blockIdx.x * 256 + threadIdx.x;  // < 16384
    int j = idx >> 5, b = idx & 31;
    float s[4];
#pragma unroll
    for (int g = 0; g < 4; g++) s[g] = g_b1[j * 4 + g];
#pragma unroll
    for (int ks = 0; ks < 16; ks++) {
        const float* p = g_part1 + ((size_t)ks * 2048 + j * 4) * 32 + b;
#pragma unroll
        for (int g = 0; g < 4; g++) s[g] += p[g * 32];
    }
    float gi = sigmoidf_(s[0]);
    float gf = sigmoidf_(s[1]);
    float gg = tanhf(s[2]);
    float go = sigmoidf_(s[3]);
    int jb = j * 32 + b;
    float c2 = gf * g_c1T[jb] + gi * gg;
    g_c1T[jb] = c2;
    float h = go * tanhf(c2);
    g_h1T[pout][jb] = h;
    g_hs[((size_t)t * 32 + b) * 512 + j] = h;
}

// ---------------- final FC: [2048,512] x [512,32000] + bias ----------------
__global__ __launch_bounds__(256) void fc_kernel(const float* __restrict__ fcw,
                                                 const float* __restrict__ fcb,
                                                 float* __restrict__ out) {
    __shared__ float As[16][132];
    __shared__ float Bs[16][132];
    int tid = threadIdx.x;
    int mb = blockIdx.y * 128, nb = blockIdx.x * 128;
    int ar = tid >> 1;
    int ak = (tid & 1) * 8;
    int ty = tid >> 4, tx = tid & 15;
    const float* Ag = g_hs + (size_t)(mb + ar) * 512 + ak;
    const float* Bg = fcw + (size_t)(nb + ar) * 512 + ak;

    unsigned long long acc[8][4];
#pragma unroll
    for (int i = 0; i < 8; i++)
#pragma unroll
        for (int jj = 0; jj < 4; jj++) acc[i][jj] = 0ull;

    for (int kt = 0; kt < 512; kt += 16) {
        float4 a0 = *(const float4*)(Ag + kt);
        float4 a1 = *(const float4*)(Ag + kt + 4);
        float4 b0 = *(const float4*)(Bg + kt);
        float4 b1 = *(const float4*)(Bg + kt + 4);
        __syncthreads();
        As[ak + 0][ar] = a0.x; As[ak + 1][ar] = a0.y; As[ak + 2][ar] = a0.z; As[ak + 3][ar] = a0.w;
        As[ak + 4][ar] = a1.x; As[ak + 5][ar] = a1.y; As[ak + 6][ar] = a1.z; As[ak + 7][ar] = a1.w;
        Bs[ak + 0][ar] = b0.x; Bs[ak + 1][ar] = b0.y; Bs[ak + 2][ar] = b0.z; Bs[ak + 3][ar] = b0.w;
        Bs[ak + 4][ar] = b1.x; Bs[ak + 5][ar] = b1.y; Bs[ak + 6][ar] = b1.z; Bs[ak + 7][ar] = b1.w;
        __syncthreads();
#pragma unroll
        for (int k = 0; k < 16; k++) {
            float4 av0 = *(const float4*)&As[k][ty * 8];
            float4 av1 = *(const float4*)&As[k][ty * 8 + 4];
            ulonglong2 bb0 = *(const ulonglong2*)&Bs[k][tx * 8];
            ulonglong2 bb1 = *(const ulonglong2*)&Bs[k][tx * 8 + 4];
            unsigned long long bv0 = bb0.x, bv1 = bb0.y, bv2 = bb1.x, bv3 = bb1.y;
            float a[8] = {av0.x, av0.y, av0.z, av0.w, av1.x, av1.y, av1.z, av1.w};
#pragma unroll
            for (int i = 0; i < 8; i++) {
                unsigned long long aa = pack2(a[i], a[i]);
                FMA2(acc[i][0], aa, bv0);
                FMA2(acc[i][1], aa, bv1);
                FMA2(acc[i][2], aa, bv2);
                FMA2(acc[i][3], aa, bv3);
            }
        }
    }

    int m0 = mb + ty * 8;
    int n0 = nb + tx * 8;
    float4 e0 = *(const float4*)(fcb + n0);
    float4 e1 = *(const float4*)(fcb + n0 + 4);
    float bias[8] = {e0.x, e0.y, e0.z, e0.w, e1.x, e1.y, e1.z, e1.w};
#pragma unroll
    for (int i = 0; i < 8; i++) {
        float c[8];
        unpack2(acc[i][0], c[0], c[1]);
        unpack2(acc[i][1], c[2], c[3]);
        unpack2(acc[i][2], c[4], c[5]);
        unpack2(acc[i][3], c[6], c[7]);
        float4 o0 = make_float4(c[0] + bias[0], c[1] + bias[1], c[2] + bias[2], c[3] + bias[3]);
        float4 o1 = make_float4(c[4] + bias[4], c[5] + bias[5], c[6] + bias[6], c[7] + bias[7]);
        size_t ro = (size_t)(m0 + i) * 32000 + n0;
        *(float4*)(out + ro) = o0;
        *(float4*)(out + ro + 4) = o1;
    }
}

// ---------------- launch ----------------
extern "C" void kernel_launch(void* const* d_in, const int* in_sizes, int n_in,
                              void* d_out, int out_size) {
    (void)in_sizes; (void)n_in; (void)out_size;
    const float* features = (const float*)d_in[0];
    const int*   captions = (const int*)d_in[1];
    const float* enc   = (const float*)d_in[3];
    const float* table = (const float*)d_in[4];
    const float* ft1w  = (const float*)d_in[5];
    const float* ft1b  = (const float*)d_in[6];
    const float* ft2w  = (const float*)d_in[7];
    const float* ft2b  = (const float*)d_in[8];
    const float* wih0  = (const float*)d_in[9];
    const float* whh0  = (const float*)d_in[10];
    const float* bih0  = (const float*)d_in[11];
    const float* bhh0  = (const float*)d_in[12];
    const float* wih1  = (const float*)d_in[13];
    const float* whh1  = (const float*)d_in[14];
    const float* bih1  = (const float*)d_in[15];
    const float* bhh1  = (const float*)d_in[16];
    const float* fcw   = (const float*)d_in[17];
    const float* fcb   = (const float*)d_in[18];
    float* out = (float*)d_out;

    prepW0_kernel<<<12288, 256>>>(wih0, whh0);
    prepW1_kernel<<<8192, 256>>>(wih1, whh1);
    prepB_kernel<<<8, 256>>>(bih0, bhh0, bih1, bhh1);
    embed_kernel<<<4096, 256>>>(captions, table);
    feat1_kernel<<<2048, 256>>>(features, ft1w, ft1b);
    feat2_kernel<<<2048, 256>>>(ft2w, ft2b);

    for (int t = 0; t < 64; t++) {
        int pin = t & 1;
        int pout = pin ^ 1;
        attn_kernel<<<32, 256>>>(enc, pin);
        lstm0_mm_kernel<<<dim3(8, 16), 256>>>(t, pin);
        lstm0_red_kernel<<<64, 256>>>(pout);
        lstm1_mm_kernel<<<dim3(8, 16), 256>>>(pin, pout);
        lstm1_red_kernel<<<64, 256>>>(t, pout);
    }

    fc_kernel<<<dim3(250, 16), 256>>>(fcw, fcb, out);
}